// round 1
// baseline (speedup 1.0000x reference)
#include <cuda_runtime.h>

// TensorNeRF forward hot path: per-ray volumetric compositing.
// One warp per ray; 512 samples strided across 32 lanes (16 chunks).
// Cumprod T via warp inclusive-scan of per-sample transmittance factors.

#define S_SAMPLES 512
#define CHUNKS (S_SAMPLES / 32)

__global__ __launch_bounds__(256) void nerf_composite_kernel(
    const float* __restrict__ rays_o,
    const float* __restrict__ rays_d,
    const float* __restrict__ sigma_feat,
    const float* __restrict__ rgb,
    const float* __restrict__ aabb,
    float* __restrict__ out,
    int N)
{
    const int gwarp = (blockIdx.x * blockDim.x + threadIdx.x) >> 5;
    const int lane  = threadIdx.x & 31;
    if (gwarp >= N) return;
    const int ray = gwarp;

    // Ray + box params (broadcast loads, L1/L2 hit across warp)
    const float ox = rays_o[ray * 3 + 0];
    const float oy = rays_o[ray * 3 + 1];
    const float oz = rays_o[ray * 3 + 2];
    const float dx = rays_d[ray * 3 + 0];
    const float dy = rays_d[ray * 3 + 1];
    const float dz = rays_d[ray * 3 + 2];
    const float ax0 = aabb[0], ay0 = aabb[1], az0 = aabb[2];
    const float ax1 = aabb[3], ay1 = aabb[4], az1 = aabb[5];

    const float NEAR = 2.0f, FAR = 6.0f;
    const float DENSITY_SHIFT = -10.0f;
    const float DISTANCE_SCALE = 25.0f;
    const float step = (FAR - NEAR) / (float)(S_SAMPLES - 1);
    const float dist = step * DISTANCE_SCALE;   // uniform spacing -> all dists equal

    const float* __restrict__ sf = sigma_feat + (size_t)ray * S_SAMPLES;
    const float* __restrict__ rg = rgb + (size_t)ray * S_SAMPLES * 3;

    float runT = 1.0f;          // running transmittance entering current chunk
    float racc = 0.0f, gacc = 0.0f, bacc = 0.0f, dacc = 0.0f;

    #pragma unroll 4
    for (int c = 0; c < CHUNKS; ++c) {
        const int s = c * 32 + lane;
        const float t = NEAR + step * (float)s;

        // in-bbox test
        const float px = ox + dx * t;
        const float py = oy + dy * t;
        const float pz = oz + dz * t;
        const bool inb = (px >= ax0) & (px <= ax1) &
                         (py >= ay0) & (py <= ay1) &
                         (pz >= az0) & (pz <= az1);

        // density: softplus(feat + shift) gated by bbox
        const float xfeat = sf[s] + DENSITY_SHIFT;
        float sp = (xfeat > 20.0f) ? xfeat : log1pf(expf(xfeat));
        const float sigma = inb ? sp : 0.0f;

        // transmittance factor + alpha (matches reference's 1 - alpha + 1e-10)
        const float e = expf(-sigma * dist);
        const float alpha = 1.0f - e;
        const float f = e + 1e-10f;

        // warp inclusive-scan product of f over the 32 samples of this chunk
        float incl = f;
        #pragma unroll
        for (int off = 1; off < 32; off <<= 1) {
            const float v = __shfl_up_sync(0xffffffffu, incl, off);
            if (lane >= off) incl *= v;
        }
        float excl = __shfl_up_sync(0xffffffffu, incl, 1);
        if (lane == 0) excl = 1.0f;

        const float w = alpha * runT * excl;

        // composite (coalesced: warp covers 384 contiguous bytes of rgb)
        racc += w * rg[s * 3 + 0];
        gacc += w * rg[s * 3 + 1];
        bacc += w * rg[s * 3 + 2];
        dacc += w * t;

        // carry running transmittance to next chunk
        runT *= __shfl_sync(0xffffffffu, incl, 31);
    }

    // warp reductions over lanes
    #pragma unroll
    for (int off = 16; off; off >>= 1) {
        racc += __shfl_down_sync(0xffffffffu, racc, off);
        gacc += __shfl_down_sync(0xffffffffu, gacc, off);
        bacc += __shfl_down_sync(0xffffffffu, bacc, off);
        dacc += __shfl_down_sync(0xffffffffu, dacc, off);
    }

    if (lane == 0) {
        out[ray * 3 + 0] = racc;                 // rgb_map
        out[ray * 3 + 1] = gacc;
        out[ray * 3 + 2] = bacc;
        out[3 * N + ray] = dacc;                 // depth_map
        out[4 * N + ray] = runT;                 // bg_weight = T[:, -1]
    }
}

extern "C" void kernel_launch(void* const* d_in, const int* in_sizes, int n_in,
                              void* d_out, int out_size) {
    const float* rays_o     = (const float*)d_in[0];
    const float* rays_d     = (const float*)d_in[1];
    const float* sigma_feat = (const float*)d_in[2];
    const float* rgb        = (const float*)d_in[3];
    const float* aabb       = (const float*)d_in[4];
    float* out = (float*)d_out;

    const int N = in_sizes[0] / 3;          // rays_o is (N, 3)
    const int warps_per_block = 256 / 32;   // 8 rays per block
    const int grid = (N + warps_per_block - 1) / warps_per_block;

    nerf_composite_kernel<<<grid, 256>>>(rays_o, rays_d, sigma_feat, rgb, aabb, out, N);
}

// round 2
// speedup vs baseline: 1.5333x; 1.5333x over previous
#include <cuda_runtime.h>

// TensorNeRF forward hot path: per-ray volumetric compositing.
// One warp per ray. Each lane owns 4 contiguous samples (float4 loads);
// 4 chunks of 128 samples. Cumprod T = in-lane prefix (3 FMULs) +
// one 5-step warp scan per chunk (4 scans total per ray).

#define S_SAMPLES 512

__global__ __launch_bounds__(256) void nerf_composite_kernel(
    const float* __restrict__ rays_o,
    const float* __restrict__ rays_d,
    const float* __restrict__ sigma_feat,
    const float* __restrict__ rgb,
    const float* __restrict__ aabb,
    float* __restrict__ out,
    int N)
{
    const int gwarp = (blockIdx.x * blockDim.x + threadIdx.x) >> 5;
    const int lane  = threadIdx.x & 31;
    if (gwarp >= N) return;
    const int ray = gwarp;

    const float ox = rays_o[ray * 3 + 0];
    const float oy = rays_o[ray * 3 + 1];
    const float oz = rays_o[ray * 3 + 2];
    const float dx = rays_d[ray * 3 + 0];
    const float dy = rays_d[ray * 3 + 1];
    const float dz = rays_d[ray * 3 + 2];
    const float ax0 = aabb[0], ay0 = aabb[1], az0 = aabb[2];
    const float ax1 = aabb[3], ay1 = aabb[4], az1 = aabb[5];

    const float NEAR = 2.0f;
    const float DENSITY_SHIFT = -10.0f;
    const float step = 4.0f / 511.0f;           // (FAR-NEAR)/(S-1)
    const float dist = step * 25.0f;            // uniform spacing

    const float4* __restrict__ sf4 = (const float4*)(sigma_feat + (size_t)ray * S_SAMPLES);
    const float4* __restrict__ rg4 = (const float4*)(rgb + (size_t)ray * S_SAMPLES * 3);

    // Prefetch all sigma features up front (max MLP, not gated by scan chain)
    float4 sv0 = sf4[lane];
    float4 sv1 = sf4[32 + lane];
    float4 sv2 = sf4[64 + lane];
    float4 sv3 = sf4[96 + lane];

    float runT = 1.0f;
    float racc = 0.0f, gacc = 0.0f, bacc = 0.0f, dacc = 0.0f;

    #pragma unroll
    for (int c = 0; c < 4; ++c) {
        const float4 sv = (c == 0) ? sv0 : (c == 1) ? sv1 : (c == 2) ? sv2 : sv3;
        const int s0 = c * 128 + lane * 4;
        const float t0 = NEAR + step * (float)s0;
        const float t1 = t0 + step;
        const float t2 = t1 + step;
        const float t3 = t2 + step;

        float f[4], alpha[4];
        const float feats[4] = {sv.x, sv.y, sv.z, sv.w};
        const float ts[4]    = {t0, t1, t2, t3};
        #pragma unroll
        for (int i = 0; i < 4; ++i) {
            const float t = ts[i];
            const float px = ox + dx * t;
            const float py = oy + dy * t;
            const float pz = oz + dz * t;
            const bool inb = (px >= ax0) & (px <= ax1) &
                             (py >= ay0) & (py <= ay1) &
                             (pz >= az0) & (pz <= az1);
            const float x = feats[i] + DENSITY_SHIFT;
            float sp = (x > 20.0f) ? x : __logf(1.0f + __expf(x));
            const float sigma = inb ? sp : 0.0f;
            const float e = __expf(-sigma * dist);
            alpha[i] = 1.0f - e;
            f[i] = e + 1e-10f;
        }

        // in-lane prefix products (exclusive): E0=1, E1=f0, E2=f0f1, E3=f0f1f2
        const float E1 = f[0];
        const float E2 = E1 * f[1];
        const float E3 = E2 * f[2];
        const float P  = E3 * f[3];     // lane product

        // warp inclusive scan of P, then exclusive
        float incl = P;
        #pragma unroll
        for (int off = 1; off < 32; off <<= 1) {
            const float v = __shfl_up_sync(0xffffffffu, incl, off);
            if (lane >= off) incl *= v;
        }
        float excl = __shfl_up_sync(0xffffffffu, incl, 1);
        if (lane == 0) excl = 1.0f;

        const float Tl = runT * excl;   // transmittance entering this lane's segment
        const float w0 = alpha[0] * Tl;
        const float w1 = alpha[1] * Tl * E1;
        const float w2 = alpha[2] * Tl * E2;
        const float w3 = alpha[3] * Tl * E3;

        // rgb: 12 contiguous floats per lane = 3 float4s (coalesced)
        const int rbase = c * 96 + lane * 3;
        const float4 r0 = rg4[rbase + 0];   // R0 G0 B0 R1
        const float4 r1 = rg4[rbase + 1];   // G1 B1 R2 G2
        const float4 r2 = rg4[rbase + 2];   // B2 R3 G3 B3

        racc += w0 * r0.x + w1 * r0.w + w2 * r1.z + w3 * r2.y;
        gacc += w0 * r0.y + w1 * r1.x + w2 * r1.w + w3 * r2.z;
        bacc += w0 * r0.z + w1 * r1.y + w2 * r2.x + w3 * r2.w;
        dacc += w0 * t0 + w1 * t1 + w2 * t2 + w3 * t3;

        runT *= __shfl_sync(0xffffffffu, incl, 31);
    }

    #pragma unroll
    for (int off = 16; off; off >>= 1) {
        racc += __shfl_down_sync(0xffffffffu, racc, off);
        gacc += __shfl_down_sync(0xffffffffu, gacc, off);
        bacc += __shfl_down_sync(0xffffffffu, bacc, off);
        dacc += __shfl_down_sync(0xffffffffu, dacc, off);
    }

    if (lane == 0) {
        out[ray * 3 + 0] = racc;
        out[ray * 3 + 1] = gacc;
        out[ray * 3 + 2] = bacc;
        out[3 * N + ray] = dacc;
        out[4 * N + ray] = runT;
    }
}

extern "C" void kernel_launch(void* const* d_in, const int* in_sizes, int n_in,
                              void* d_out, int out_size) {
    const float* rays_o     = (const float*)d_in[0];
    const float* rays_d     = (const float*)d_in[1];
    const float* sigma_feat = (const float*)d_in[2];
    const float* rgb        = (const float*)d_in[3];
    const float* aabb       = (const float*)d_in[4];
    float* out = (float*)d_out;

    const int N = in_sizes[0] / 3;
    const int warps_per_block = 256 / 32;
    const int grid = (N + warps_per_block - 1) / warps_per_block;

    nerf_composite_kernel<<<grid, 256>>>(rays_o, rays_d, sigma_feat, rgb, aabb, out, N);
}

// round 3
// speedup vs baseline: 4.0474x; 2.6396x over previous
#include <cuda_runtime.h>

// TensorNeRF compositing, interval-culled.
// Key fact: out-of-bbox samples have sigma==0 -> alpha==0 -> cumprod factor
// (1 - 0 + 1e-10) rounds to exactly 1.0f in float32, so they contribute
// nothing to weights, rgb, depth, or bg_weight. The in-bbox set along a ray
// is an index interval (fma is weakly monotone in t), found by ballot scan.
// Phase A: pure-ALU interval search (no loads). Phase B: composite only the
// covered chunks (typically 0-5 of 16).

#define S_SAMPLES 512

__global__ __launch_bounds__(256) void nerf_composite_kernel(
    const float* __restrict__ rays_o,
    const float* __restrict__ rays_d,
    const float* __restrict__ sigma_feat,
    const float* __restrict__ rgb,
    const float* __restrict__ aabb,
    float* __restrict__ out,
    int N)
{
    const int gwarp = (blockIdx.x * blockDim.x + threadIdx.x) >> 5;
    const int lane  = threadIdx.x & 31;
    if (gwarp >= N) return;
    const int ray = gwarp;

    const float ox = rays_o[ray * 3 + 0];
    const float oy = rays_o[ray * 3 + 1];
    const float oz = rays_o[ray * 3 + 2];
    const float dx = rays_d[ray * 3 + 0];
    const float dy = rays_d[ray * 3 + 1];
    const float dz = rays_d[ray * 3 + 2];
    const float ax0 = aabb[0], ay0 = aabb[1], az0 = aabb[2];
    const float ax1 = aabb[3], ay1 = aabb[4], az1 = aabb[5];

    const float NEAR = 2.0f;
    const float DENSITY_SHIFT = -10.0f;
    const float step = 4.0f / 511.0f;
    const float dist = step * 25.0f;

    // ---- Phase A: find in-bbox sample interval via ballot scan (no loads) ----
    int first = -1, last = -1;
    #pragma unroll 1
    for (int c = 0; c < 16; ++c) {
        const int s = c * 32 + lane;
        const float t = fmaf(step, (float)s, NEAR);
        const float px = fmaf(dx, t, ox);
        const float py = fmaf(dy, t, oy);
        const float pz = fmaf(dz, t, oz);
        const bool inb = (px >= ax0) & (px <= ax1) &
                         (py >= ay0) & (py <= ay1) &
                         (pz >= az0) & (pz <= az1);
        const unsigned mask = __ballot_sync(0xffffffffu, inb);
        if (mask) {
            if (first < 0) first = c * 32 + (__ffs(mask) - 1);
            last = c * 32 + (31 - __clz(mask));
        } else if (first >= 0) {
            break;   // interval ended; nothing further can be in-box
        }
    }

    if (first < 0) {
        // No in-box samples: all weights exactly 0, T stays exactly 1.0f.
        if (lane == 0) {
            out[ray * 3 + 0] = 0.0f;
            out[ray * 3 + 1] = 0.0f;
            out[ray * 3 + 2] = 0.0f;
            out[3 * N + ray] = 0.0f;
            out[4 * N + ray] = 1.0f;
        }
        return;
    }

    // ---- Phase B: composite only covered chunks ----
    const int c0 = first >> 5;
    const int c1 = last >> 5;

    const float* __restrict__ sf = sigma_feat + (size_t)ray * S_SAMPLES;
    const float* __restrict__ rg = rgb + (size_t)ray * S_SAMPLES * 3;

    float runT = 1.0f;
    float racc = 0.0f, gacc = 0.0f, bacc = 0.0f, dacc = 0.0f;

    #pragma unroll 1
    for (int c = c0; c <= c1; ++c) {
        const int s = c * 32 + lane;
        const float t = fmaf(step, (float)s, NEAR);
        const float px = fmaf(dx, t, ox);
        const float py = fmaf(dy, t, oy);
        const float pz = fmaf(dz, t, oz);
        const bool inb = (px >= ax0) & (px <= ax1) &
                         (py >= ay0) & (py <= ay1) &
                         (pz >= az0) & (pz <= az1);

        const float x = sf[s] + DENSITY_SHIFT;
        float sp = (x > 20.0f) ? x : __logf(1.0f + __expf(x));
        const float sigma = inb ? sp : 0.0f;

        const float e = __expf(-sigma * dist);
        const float alpha = 1.0f - e;
        const float f = e + 1e-10f;

        float incl = f;
        #pragma unroll
        for (int off = 1; off < 32; off <<= 1) {
            const float v = __shfl_up_sync(0xffffffffu, incl, off);
            if (lane >= off) incl *= v;
        }
        float excl = __shfl_up_sync(0xffffffffu, incl, 1);
        if (lane == 0) excl = 1.0f;

        const float w = alpha * runT * excl;

        racc += w * rg[s * 3 + 0];
        gacc += w * rg[s * 3 + 1];
        bacc += w * rg[s * 3 + 2];
        dacc += w * t;

        runT *= __shfl_sync(0xffffffffu, incl, 31);
    }

    #pragma unroll
    for (int off = 16; off; off >>= 1) {
        racc += __shfl_down_sync(0xffffffffu, racc, off);
        gacc += __shfl_down_sync(0xffffffffu, gacc, off);
        bacc += __shfl_down_sync(0xffffffffu, bacc, off);
        dacc += __shfl_down_sync(0xffffffffu, dacc, off);
    }

    if (lane == 0) {
        out[ray * 3 + 0] = racc;
        out[ray * 3 + 1] = gacc;
        out[ray * 3 + 2] = bacc;
        out[3 * N + ray] = dacc;
        out[4 * N + ray] = runT;   // bg_weight: factors after interval are exactly 1.0f
    }
}

extern "C" void kernel_launch(void* const* d_in, const int* in_sizes, int n_in,
                              void* d_out, int out_size) {
    const float* rays_o     = (const float*)d_in[0];
    const float* rays_d     = (const float*)d_in[1];
    const float* sigma_feat = (const float*)d_in[2];
    const float* rgb        = (const float*)d_in[3];
    const float* aabb       = (const float*)d_in[4];
    float* out = (float*)d_out;

    const int N = in_sizes[0] / 3;
    const int warps_per_block = 256 / 32;
    const int grid = (N + warps_per_block - 1) / warps_per_block;

    nerf_composite_kernel<<<grid, 256>>>(rays_o, rays_d, sigma_feat, rgb, aabb, out, N);
}

// round 5
// speedup vs baseline: 4.9730x; 1.2287x over previous
#include <cuda_runtime.h>

// TensorNeRF compositing, analytic slab-culled.
// Out-of-bbox samples: sigma==0 -> factor (1-0+1e-10) == 1.0f exactly in f32,
// so they contribute nothing. The in-box t-range is found analytically
// (ray/AABB slab test, ~40 FLOPs, no memory); a +-2-sample safety margin makes
// the chunk range conservative, and the exact per-sample bbox predicate inside
// the composite loop preserves bit-level gating semantics.

#define S_SAMPLES 512

__global__ __launch_bounds__(256) void nerf_composite_kernel(
    const float* __restrict__ rays_o,
    const float* __restrict__ rays_d,
    const float* __restrict__ sigma_feat,
    const float* __restrict__ rgb,
    const float* __restrict__ aabb,
    float* __restrict__ out,
    int N)
{
    const int gwarp = (blockIdx.x * blockDim.x + threadIdx.x) >> 5;
    const int lane  = threadIdx.x & 31;
    if (gwarp >= N) return;
    const int ray = gwarp;

    const float ox = rays_o[ray * 3 + 0];
    const float oy = rays_o[ray * 3 + 1];
    const float oz = rays_o[ray * 3 + 2];
    const float dx = rays_d[ray * 3 + 0];
    const float dy = rays_d[ray * 3 + 1];
    const float dz = rays_d[ray * 3 + 2];
    const float ax0 = aabb[0], ay0 = aabb[1], az0 = aabb[2];
    const float ax1 = aabb[3], ay1 = aabb[4], az1 = aabb[5];

    const float NEAR = 2.0f, FAR = 6.0f;
    const float DENSITY_SHIFT = -10.0f;
    const float step = 4.0f / 511.0f;
    const float dist = step * 25.0f;

    // ---- Analytic slab test (per-lane redundant; no divergence) ----
    const float idx_ = __frcp_rn(dx);
    const float idy_ = __frcp_rn(dy);
    const float idz_ = __frcp_rn(dz);
    const float txa = (ax0 - ox) * idx_, txb = (ax1 - ox) * idx_;
    const float tya = (ay0 - oy) * idy_, tyb = (ay1 - oy) * idy_;
    const float tza = (az0 - oz) * idz_, tzb = (az1 - oz) * idz_;
    float t_ent = fmaxf(fmaxf(fminf(txa, txb), fminf(tya, tyb)), fminf(tza, tzb));
    float t_exi = fminf(fminf(fmaxf(txa, txb), fmaxf(tya, tyb)), fmaxf(tza, tzb));
    t_ent = fmaxf(t_ent, NEAR);
    t_exi = fminf(t_exi, FAR);

    // Conservative sample-index window with +-2 sample margin.
    const float margin = 2.0f * step;
    bool miss = (t_ent > t_exi + margin);

    int c0 = 0, c1 = -1;
    if (!miss) {
        int s_lo = __float2int_rd((t_ent - NEAR) * (511.0f / 4.0f)) - 2;
        int s_hi = __float2int_ru((t_exi - NEAR) * (511.0f / 4.0f)) + 2;
        s_lo = max(s_lo, 0);
        s_hi = min(s_hi, S_SAMPLES - 1);
        if (s_lo > s_hi) miss = true;
        else { c0 = s_lo >> 5; c1 = s_hi >> 5; }
    }

    if (miss) {
        if (lane == 0) {
            out[ray * 3 + 0] = 0.0f;
            out[ray * 3 + 1] = 0.0f;
            out[ray * 3 + 2] = 0.0f;
            out[3 * N + ray] = 0.0f;
            out[4 * N + ray] = 1.0f;
        }
        return;
    }

    // ---- Composite over covered chunks only (exact per-sample gating) ----
    const float* __restrict__ sf = sigma_feat + (size_t)ray * S_SAMPLES;
    const float* __restrict__ rg = rgb + (size_t)ray * S_SAMPLES * 3;

    float runT = 1.0f;
    float racc = 0.0f, gacc = 0.0f, bacc = 0.0f, dacc = 0.0f;

    #pragma unroll 1
    for (int c = c0; c <= c1; ++c) {
        const int s = c * 32 + lane;
        const float t = fmaf(step, (float)s, NEAR);
        const float px = fmaf(dx, t, ox);
        const float py = fmaf(dy, t, oy);
        const float pz = fmaf(dz, t, oz);
        const bool inb = (px >= ax0) & (px <= ax1) &
                         (py >= ay0) & (py <= ay1) &
                         (pz >= az0) & (pz <= az1);

        const float x = sf[s] + DENSITY_SHIFT;
        float sp = (x > 20.0f) ? x : __logf(1.0f + __expf(x));
        const float sigma = inb ? sp : 0.0f;

        const float e = __expf(-sigma * dist);
        const float alpha = 1.0f - e;
        const float f = e + 1e-10f;

        float incl = f;
        #pragma unroll
        for (int off = 1; off < 32; off <<= 1) {
            const float v = __shfl_up_sync(0xffffffffu, incl, off);
            if (lane >= off) incl *= v;
        }
        float excl = __shfl_up_sync(0xffffffffu, incl, 1);
        if (lane == 0) excl = 1.0f;

        const float w = alpha * runT * excl;

        racc += w * rg[s * 3 + 0];
        gacc += w * rg[s * 3 + 1];
        bacc += w * rg[s * 3 + 2];
        dacc += w * t;

        runT *= __shfl_sync(0xffffffffu, incl, 31);
    }

    #pragma unroll
    for (int off = 16; off; off >>= 1) {
        racc += __shfl_down_sync(0xffffffffu, racc, off);
        gacc += __shfl_down_sync(0xffffffffu, gacc, off);
        bacc += __shfl_down_sync(0xffffffffu, bacc, off);
        dacc += __shfl_down_sync(0xffffffffu, dacc, off);
    }

    if (lane == 0) {
        out[ray * 3 + 0] = racc;
        out[ray * 3 + 1] = gacc;
        out[ray * 3 + 2] = bacc;
        out[3 * N + ray] = dacc;
        out[4 * N + ray] = runT;
    }
}

extern "C" void kernel_launch(void* const* d_in, const int* in_sizes, int n_in,
                              void* d_out, int out_size) {
    const float* rays_o     = (const float*)d_in[0];
    const float* rays_d     = (const float*)d_in[1];
    const float* sigma_feat = (const float*)d_in[2];
    const float* rgb        = (const float*)d_in[3];
    const float* aabb       = (const float*)d_in[4];
    float* out = (float*)d_out;

    const int N = in_sizes[0] / 3;
    const int warps_per_block = 256 / 32;
    const int grid = (N + warps_per_block - 1) / warps_per_block;

    nerf_composite_kernel<<<grid, 256>>>(rays_o, rays_d, sigma_feat, rgb, aabb, out, N);
}